// round 1
// baseline (speedup 1.0000x reference)
#include <cuda_runtime.h>

// Problem constants
#define LL 2
#define BB 16
#define TT 512
#define HH 12
#define NL 4096   // (1+1)^12 leaves
#define NC 1000

// Scratch: per-batch mean leaf vector (16 x 4096 floats = 256 KB)
__device__ float g_avg[BB * NL];

// ---------------------------------------------------------------------------
// Kernel 0: zero scratch + output (both accumulated via atomicAdd later)
// ---------------------------------------------------------------------------
__global__ void zero_kernel(float* __restrict__ out) {
    int i = blockIdx.x * blockDim.x + threadIdx.x;
    if (i < BB * NL) g_avg[i] = 0.f;
    if (i < BB * NC) out[i] = 0.f;
}

// ---------------------------------------------------------------------------
// Kernel 1: accumulate mean leaf vectors.
// grid = B * (T/64) = 128 blocks, 256 threads.
// Per token: P_hi[u] = prod_{i=0..5} f(i, bit), P_lo[v] = prod_{i=6..11} f(i, bit)
// where f(i,0)=x_i, f(i,1)=2*x_i - cut_i.  leaf[u*64+v] = P_hi[u]*P_lo[v].
// Warp w owns u in [8w, 8w+8); lanes own v = lane, lane+32.
// ---------------------------------------------------------------------------
__global__ __launch_bounds__(256) void leaf_accum_kernel(
    const float* __restrict__ x, const float* __restrict__ cuts)
{
    const int b     = blockIdx.x >> 3;   // batch
    const int chunk = blockIdx.x & 7;    // token chunk of 64

    __shared__ float P[64 * 128];        // [tok][half*64 + u]  (32 KB)
    __shared__ float sx[64 * 12];        // x values for 64 tokens
    __shared__ float sc[12];             // cuts

    const int tid = threadIdx.x;
    if (tid < 12) sc[tid] = cuts[tid];

    // x[-1] slice: offset (L-1)*B*T*H, token row stride H
    const float* xl = x + (size_t)(LL - 1) * BB * TT * HH
                        + ((size_t)b * TT + (size_t)chunk * 64) * HH;
    for (int i = tid; i < 64 * 12; i += 256) sx[i] = xl[i];
    __syncthreads();

    // Phase A: 64 tokens x 2 halves x 64 indices = 8192 partial products
    for (int e = tid; e < 8192; e += 256) {
        const int tok  = e >> 7;
        const int half = (e >> 6) & 1;
        const int u    = e & 63;
        const float* xr = sx + tok * 12 + half * 6;
        const float* cr = sc + half * 6;
        float p = 1.f;
#pragma unroll
        for (int i = 0; i < 6; i++) {
            const float xv = xr[i];
            const float f  = ((u >> (5 - i)) & 1) ? fmaf(2.f, xv, -cr[i]) : xv;
            p *= f;
        }
        P[e] = p;
    }
    __syncthreads();

    // Phase B: rank-1 accumulation into per-warp register tiles
    const int w = tid >> 5, lane = tid & 31;
    float acc[8][2];
#pragma unroll
    for (int i = 0; i < 8; i++) { acc[i][0] = 0.f; acc[i][1] = 0.f; }

    for (int tok = 0; tok < 64; tok++) {
        const float* Pr = P + tok * 128;
        const float4 pa = *(const float4*)(Pr + 8 * w);
        const float4 pb = *(const float4*)(Pr + 8 * w + 4);
        const float plo0 = Pr[64 + lane];
        const float plo1 = Pr[64 + lane + 32];
        const float ph[8] = {pa.x, pa.y, pa.z, pa.w, pb.x, pb.y, pb.z, pb.w};
#pragma unroll
        for (int uu = 0; uu < 8; uu++) {
            acc[uu][0] = fmaf(ph[uu], plo0, acc[uu][0]);
            acc[uu][1] = fmaf(ph[uu], plo1, acc[uu][1]);
        }
    }

    // Write (scaled by 1/T for the mean); 8 chunks per batch collide -> atomics
    const float s = 1.f / (float)TT;
    float* dst = g_avg + b * NL;
#pragma unroll
    for (int uu = 0; uu < 8; uu++) {
        const int u = 8 * w + uu;
        atomicAdd(dst + u * 64 + lane,      acc[uu][0] * s);
        atomicAdd(dst + u * 64 + lane + 32, acc[uu][1] * s);
    }
}

// ---------------------------------------------------------------------------
// Kernel 2: out[16,1000] = g_avg[16,4096] @ score[4096,1000], split-K atomics.
// grid = (32 l-chunks of 128, 4 c-tiles of 256), 256 threads.
// Thread: bg = tid>>6 owns 4 batches (bg*4..bg*4+3), ci = tid&63 owns 4 cols.
// Per l: LDS.128 of avg (4 b), LDG.128 of score (4 c), 16 FMAs.
// ---------------------------------------------------------------------------
#define LCHUNK 128
#define CTILE  256

__global__ __launch_bounds__(256) void gemm_out_kernel(
    const float* __restrict__ score, float* __restrict__ out)
{
    __shared__ float sA[LCHUNK * 16];    // [l][b]  (8 KB)

    const int tid = threadIdx.x;
    const int l0  = blockIdx.x * LCHUNK;
    const int c0  = blockIdx.y * CTILE;

    // Load avg chunk, transpose to [l][b] for broadcast float4 reads
    for (int e = tid; e < 16 * LCHUNK; e += 256) {
        const int bb = e >> 7;       // 0..15
        const int l  = e & (LCHUNK - 1);
        sA[l * 16 + bb] = g_avg[bb * NL + l0 + l];
    }
    __syncthreads();

    const int bg = tid >> 6;         // batch group (4 batches)
    const int ci = tid & 63;         // column group
    const int c  = c0 + ci * 4;
    if (c >= NC) return;             // NC divisible by 4 -> full float4 or none

    float acc[4][4];
#pragma unroll
    for (int k = 0; k < 4; k++)
#pragma unroll
        for (int j = 0; j < 4; j++) acc[k][j] = 0.f;

    const float* sp = score + (size_t)l0 * NC + c;
    const float* ap = sA + bg * 4;

#pragma unroll 4
    for (int l = 0; l < LCHUNK; l++) {
        const float4 sv = *(const float4*)(sp);
        sp += NC;
        const float4 av = *(const float4*)(ap + l * 16);
        const float a[4]  = {av.x, av.y, av.z, av.w};
        const float ss[4] = {sv.x, sv.y, sv.z, sv.w};
#pragma unroll
        for (int k = 0; k < 4; k++)
#pragma unroll
            for (int j = 0; j < 4; j++)
                acc[k][j] = fmaf(a[k], ss[j], acc[k][j]);
    }

#pragma unroll
    for (int k = 0; k < 4; k++) {
        const int bb = bg * 4 + k;
#pragma unroll
        for (int j = 0; j < 4; j++)
            atomicAdd(out + bb * NC + c + j, acc[k][j]);
    }
}

// ---------------------------------------------------------------------------
extern "C" void kernel_launch(void* const* d_in, const int* in_sizes, int n_in,
                              void* d_out, int out_size)
{
    const float* x     = (const float*)d_in[0];  // (2,16,512,12)
    const float* cuts  = (const float*)d_in[1];  // (12,1)
    const float* score = (const float*)d_in[2];  // (4096,1000)
    float* out = (float*)d_out;                  // (16,1000)

    zero_kernel<<<(BB * NL + 255) / 256, 256>>>(out);
    leaf_accum_kernel<<<BB * (TT / 64), 256>>>(x, cuts);
    dim3 g2(NL / LCHUNK, (NC + CTILE - 1) / CTILE);
    gemm_out_kernel<<<g2, 256>>>(score, out);
}

// round 2
// speedup vs baseline: 1.3872x; 1.3872x over previous
#include <cuda_runtime.h>

// Problem constants
#define LL 2
#define BB 16
#define TT 512
#define HH 12
#define NL 4096   // (1+1)^12 leaves
#define NC 1000
#define NCHUNK 8  // token chunks of 64 per batch

// Disjoint partial sums: [chunk][batch][leaf]  (2 MB)
__device__ float g_part[NCHUNK * BB * NL];

// ---- f32x2 helpers (packed dual-FMA: 2 fp32 FMAs per instruction) ----------
__device__ __forceinline__ unsigned long long pk2(float x, float y) {
    unsigned long long r;
    asm("mov.b64 %0, {%1, %2};" : "=l"(r) : "f"(x), "f"(y));
    return r;
}
__device__ __forceinline__ void fma2(unsigned long long& d,
                                     unsigned long long a,
                                     unsigned long long b) {
    asm("fma.rn.f32x2 %0, %1, %2, %0;" : "+l"(d) : "l"(a), "l"(b));
}
__device__ __forceinline__ void upk2(unsigned long long v, float& lo, float& hi) {
    asm("mov.b64 {%0, %1}, %2;" : "=f"(lo), "=f"(hi) : "l"(v));
}

// ---------------------------------------------------------------------------
// Kernel 1: per-(batch, token-chunk) partial mean-leaf vectors (disjoint STG),
// plus zeroing of `out` (stream order guarantees visibility to kernel 2).
// grid = B * NCHUNK = 128 blocks, 256 threads.
// leaf index l = u*64+v: u = high 6 tree levels, v = low 6 levels.
// f(i,0)=x_i (W=1), f(i,1)=2*x_i - cut_i (W=2, b=-cut).
// ---------------------------------------------------------------------------
__global__ __launch_bounds__(256) void leaf_kernel(
    const float* __restrict__ x, const float* __restrict__ cuts,
    float* __restrict__ out)
{
    const int tid = threadIdx.x;
    // Fold in zeroing of out (16 x 1000): 128 blocks x 256 threads = 32768 >= 16000
    const int gid = blockIdx.x * 256 + tid;
    if (gid < BB * NC) out[gid] = 0.f;

    const int b     = blockIdx.x >> 3;   // batch
    const int chunk = blockIdx.x & 7;    // token chunk of 64

    __shared__ float P[64 * 128];        // [tok][half*64 + u]  (32 KB)
    __shared__ float sx[64 * 12];
    __shared__ float sc[12];

    if (tid < 12) sc[tid] = cuts[tid];

    const float* xl = x + (size_t)(LL - 1) * BB * TT * HH
                        + ((size_t)b * TT + (size_t)chunk * 64) * HH;
    for (int i = tid; i < 64 * 12; i += 256) sx[i] = xl[i];
    __syncthreads();

    // Phase A: 64 tokens x 2 halves x 64 half-leaf products
    for (int e = tid; e < 8192; e += 256) {
        const int tok  = e >> 7;
        const int half = (e >> 6) & 1;
        const int u    = e & 63;
        const float* xr = sx + tok * 12 + half * 6;
        const float* cr = sc + half * 6;
        float p = 1.f;
#pragma unroll
        for (int i = 0; i < 6; i++) {
            const float xv = xr[i];
            const float f  = ((u >> (5 - i)) & 1) ? fmaf(2.f, xv, -cr[i]) : xv;
            p *= f;
        }
        P[e] = p;
    }
    __syncthreads();

    // Phase B: rank-1 accumulation, packed f32x2 (pairs along u)
    const int w = tid >> 5, lane = tid & 31;
    unsigned long long acc2[4][2];
#pragma unroll
    for (int p = 0; p < 4; p++) { acc2[p][0] = 0ull; acc2[p][1] = 0ull; }

    for (int tok = 0; tok < 64; tok++) {
        const float* Pr = P + tok * 128;
        const float4 pa = *(const float4*)(Pr + 8 * w);
        const float4 pb = *(const float4*)(Pr + 8 * w + 4);
        const float plo0 = Pr[64 + lane];
        const float plo1 = Pr[64 + lane + 32];
        const unsigned long long pl0 = pk2(plo0, plo0);
        const unsigned long long pl1 = pk2(plo1, plo1);
        const unsigned long long ph01 = pk2(pa.x, pa.y);
        const unsigned long long ph23 = pk2(pa.z, pa.w);
        const unsigned long long ph45 = pk2(pb.x, pb.y);
        const unsigned long long ph67 = pk2(pb.z, pb.w);
        fma2(acc2[0][0], ph01, pl0); fma2(acc2[0][1], ph01, pl1);
        fma2(acc2[1][0], ph23, pl0); fma2(acc2[1][1], ph23, pl1);
        fma2(acc2[2][0], ph45, pl0); fma2(acc2[2][1], ph45, pl1);
        fma2(acc2[3][0], ph67, pl0); fma2(acc2[3][1], ph67, pl1);
    }

    // Plain stores to this block's private partial slice (pre-scaled by 1/T)
    const float s = 1.f / (float)TT;
    float* dst = g_part + ((size_t)(chunk * BB + b)) * NL;
#pragma unroll
    for (int p = 0; p < 4; p++) {
        float u0v0, u1v0, u0v1, u1v1;
        upk2(acc2[p][0], u0v0, u1v0);
        upk2(acc2[p][1], u0v1, u1v1);
        const int u0 = 8 * w + 2 * p;
        dst[u0 * 64 + lane]            = u0v0 * s;
        dst[u0 * 64 + lane + 32]       = u0v1 * s;
        dst[(u0 + 1) * 64 + lane]      = u1v0 * s;
        dst[(u0 + 1) * 64 + lane + 32] = u1v1 * s;
    }
}

// ---------------------------------------------------------------------------
// Kernel 2: out[16,1000] += avg[16,4096] @ score[4096,1000], split-K atomics.
// avg is materialized per-block in smem by summing the 8 chunk partials.
// grid = (NL/LCHUNK, 4) = (64, 4) = 256 blocks, 256 threads.
// Thread: bg = tid>>6 owns batches [4bg,4bg+4), ci = tid&63 owns cols [c,c+4).
// Inner: 1 LDG.128 (score) + 2 LDS.64 (avg pairs) + 4 packs + 8 f32x2 FMAs.
// ---------------------------------------------------------------------------
#define LCHUNK 64
#define CTILE  256

__global__ __launch_bounds__(256) void gemm_out_kernel(
    const float* __restrict__ score, float* __restrict__ out)
{
    __shared__ float sA[LCHUNK * 16];    // [l][b]  (4 KB)

    const int tid = threadIdx.x;
    const int l0  = blockIdx.x * LCHUNK;
    const int c0  = blockIdx.y * CTILE;

    // Build avg chunk in smem: sum the 8 disjoint partials, layout [l][b]
    for (int e = tid; e < 16 * LCHUNK; e += 256) {
        const int bb = e >> 6;           // 0..15
        const int l  = e & (LCHUNK - 1);
        const float* p = g_part + (size_t)bb * NL + l0 + l;
        float v = 0.f;
#pragma unroll
        for (int ch = 0; ch < NCHUNK; ch++)
            v += p[(size_t)ch * BB * NL];
        sA[l * 16 + bb] = v;
    }
    __syncthreads();

    const int bg = tid >> 6;             // batch group of 4
    const int ci = tid & 63;
    const int c  = c0 + ci * 4;
    if (c >= NC) return;                 // NC%4==0 -> full float4 or none

    unsigned long long acc2[4][2];       // [col j][batch pair]
#pragma unroll
    for (int j = 0; j < 4; j++) { acc2[j][0] = 0ull; acc2[j][1] = 0ull; }

    const float* sp = score + (size_t)l0 * NC + c;
    const unsigned long long* ap =
        (const unsigned long long*)(sA + bg * 4);   // 2 ull per row of 16 floats

#pragma unroll 4
    for (int l = 0; l < LCHUNK; l++) {
        const float4 sv = *(const float4*)sp;
        sp += NC;
        const unsigned long long a01 = ap[l * 8 + 0];
        const unsigned long long a23 = ap[l * 8 + 1];
        const unsigned long long s00 = pk2(sv.x, sv.x);
        const unsigned long long s11 = pk2(sv.y, sv.y);
        const unsigned long long s22 = pk2(sv.z, sv.z);
        const unsigned long long s33 = pk2(sv.w, sv.w);
        fma2(acc2[0][0], s00, a01); fma2(acc2[0][1], s00, a23);
        fma2(acc2[1][0], s11, a01); fma2(acc2[1][1], s11, a23);
        fma2(acc2[2][0], s22, a01); fma2(acc2[2][1], s22, a23);
        fma2(acc2[3][0], s33, a01); fma2(acc2[3][1], s33, a23);
    }

#pragma unroll
    for (int j = 0; j < 4; j++) {
        float b0, b1, b2, b3;
        upk2(acc2[j][0], b0, b1);
        upk2(acc2[j][1], b2, b3);
        const int bb = bg * 4;
        atomicAdd(out + (bb + 0) * NC + c + j, b0);
        atomicAdd(out + (bb + 1) * NC + c + j, b1);
        atomicAdd(out + (bb + 2) * NC + c + j, b2);
        atomicAdd(out + (bb + 3) * NC + c + j, b3);
    }
}

// ---------------------------------------------------------------------------
extern "C" void kernel_launch(void* const* d_in, const int* in_sizes, int n_in,
                              void* d_out, int out_size)
{
    const float* x     = (const float*)d_in[0];  // (2,16,512,12)
    const float* cuts  = (const float*)d_in[1];  // (12,1)
    const float* score = (const float*)d_in[2];  // (4096,1000)
    float* out = (float*)d_out;                  // (16,1000)

    leaf_kernel<<<BB * NCHUNK, 256>>>(x, cuts, out);
    dim3 g2(NL / LCHUNK, (NC + CTILE - 1) / CTILE);
    gemm_out_kernel<<<g2, 256>>>(score, out);
}

// round 3
// speedup vs baseline: 1.7722x; 1.2775x over previous
#include <cuda_runtime.h>

// Problem constants
#define LL 2
#define BB 16
#define TT 512
#define HH 12
#define NL 4096   // (1+1)^12 leaves
#define NC 1000
#define NCHUNK 16 // token chunks of 32 per batch
#define TOKC 32   // tokens per chunk

// Disjoint partial sums: [chunk][batch][leaf]  (4 MB)
__device__ float g_part[NCHUNK * BB * NL];

// ---- f32x2 helpers (packed dual-FMA) ---------------------------------------
__device__ __forceinline__ unsigned long long pk2(float x, float y) {
    unsigned long long r;
    asm("mov.b64 %0, {%1, %2};" : "=l"(r) : "f"(x), "f"(y));
    return r;
}
__device__ __forceinline__ void fma2(unsigned long long& d,
                                     unsigned long long a,
                                     unsigned long long b) {
    asm("fma.rn.f32x2 %0, %1, %2, %0;" : "+l"(d) : "l"(a), "l"(b));
}
__device__ __forceinline__ void upk2(unsigned long long v, float& lo, float& hi) {
    asm("mov.b64 {%0, %1}, %2;" : "=f"(lo), "=f"(hi) : "l"(v));
}

// ---------------------------------------------------------------------------
// Kernel 1: per-(batch, token-chunk) partial mean-leaf vectors, disjoint STG.
// grid = B * NCHUNK = 256 blocks, 256 threads. Also zeroes `out`.
// ---------------------------------------------------------------------------
__global__ __launch_bounds__(256) void leaf_kernel(
    const float* __restrict__ x, const float* __restrict__ cuts,
    float* __restrict__ out)
{
    const int tid = threadIdx.x;
    const int gid = blockIdx.x * 256 + tid;    // 256*256 = 65536 >= 16000
    if (gid < BB * NC) out[gid] = 0.f;

    const int b     = blockIdx.x >> 4;         // batch
    const int chunk = blockIdx.x & 15;         // token chunk of 32

    __shared__ float P[TOKC * 128];            // [tok][half*64 + u]  (16 KB)
    __shared__ float sx[TOKC * 12];
    __shared__ float sc[12];

    if (tid < 12) sc[tid] = cuts[tid];

    const float* xl = x + (size_t)(LL - 1) * BB * TT * HH
                        + ((size_t)b * TT + (size_t)chunk * TOKC) * HH;
    for (int i = tid; i < TOKC * 12; i += 256) sx[i] = xl[i];
    __syncthreads();

    // Phase A: TOKC tokens x 2 halves x 64 half-leaf products
    for (int e = tid; e < TOKC * 128; e += 256) {
        const int tok  = e >> 7;
        const int half = (e >> 6) & 1;
        const int u    = e & 63;
        const float* xr = sx + tok * 12 + half * 6;
        const float* cr = sc + half * 6;
        float p = 1.f;
#pragma unroll
        for (int i = 0; i < 6; i++) {
            const float xv = xr[i];
            const float f  = ((u >> (5 - i)) & 1) ? fmaf(2.f, xv, -cr[i]) : xv;
            p *= f;
        }
        P[e] = p;
    }
    __syncthreads();

    // Phase B: rank-1 accumulation with packed f32x2
    const int w = tid >> 5, lane = tid & 31;
    unsigned long long acc2[4][2];
#pragma unroll
    for (int p = 0; p < 4; p++) { acc2[p][0] = 0ull; acc2[p][1] = 0ull; }

    for (int tok = 0; tok < TOKC; tok++) {
        const float* Pr = P + tok * 128;
        const float4 pa = *(const float4*)(Pr + 8 * w);
        const float4 pb = *(const float4*)(Pr + 8 * w + 4);
        const float plo0 = Pr[64 + lane];
        const float plo1 = Pr[64 + lane + 32];
        const unsigned long long pl0 = pk2(plo0, plo0);
        const unsigned long long pl1 = pk2(plo1, plo1);
        const unsigned long long ph01 = pk2(pa.x, pa.y);
        const unsigned long long ph23 = pk2(pa.z, pa.w);
        const unsigned long long ph45 = pk2(pb.x, pb.y);
        const unsigned long long ph67 = pk2(pb.z, pb.w);
        fma2(acc2[0][0], ph01, pl0); fma2(acc2[0][1], ph01, pl1);
        fma2(acc2[1][0], ph23, pl0); fma2(acc2[1][1], ph23, pl1);
        fma2(acc2[2][0], ph45, pl0); fma2(acc2[2][1], ph45, pl1);
        fma2(acc2[3][0], ph67, pl0); fma2(acc2[3][1], ph67, pl1);
    }

    const float s = 1.f / (float)TT;
    float* dst = g_part + ((size_t)(chunk * BB + b)) * NL;
#pragma unroll
    for (int p = 0; p < 4; p++) {
        float u0v0, u1v0, u0v1, u1v1;
        upk2(acc2[p][0], u0v0, u1v0);
        upk2(acc2[p][1], u0v1, u1v1);
        const int u0 = 8 * w + 2 * p;
        dst[u0 * 64 + lane]            = u0v0 * s;
        dst[u0 * 64 + lane + 32]       = u0v1 * s;
        dst[(u0 + 1) * 64 + lane]      = u1v0 * s;
        dst[(u0 + 1) * 64 + lane + 32] = u1v1 * s;
    }
}

// ---------------------------------------------------------------------------
// Kernel 2: out[16,1000] += avg[16,4096] @ score[4096,1000], split-K atomics.
// grid = (NL/LCHUNK, 4) = (64, 4), 256 threads.
// Inner loop: double-buffered batches of 8 LDG.128 (explicit MLP=8).
// ---------------------------------------------------------------------------
#define LCHUNK 64
#define CTILE  256
#define MB 8      // load batch size

__global__ __launch_bounds__(256) void gemm_out_kernel(
    const float* __restrict__ score, float* __restrict__ out)
{
    __shared__ float sA[LCHUNK * 16];    // [l][b]  (4 KB)

    const int tid = threadIdx.x;
    const int l0  = blockIdx.x * LCHUNK;
    const int c0  = blockIdx.y * CTILE;

    // Build avg chunk in smem: sum 16 disjoint partials (L2-hot), layout [l][b]
    for (int e = tid; e < 16 * LCHUNK; e += 256) {
        const int bb = e >> 6;           // 0..15
        const int l  = e & (LCHUNK - 1);
        const float* p = g_part + (size_t)bb * NL + l0 + l;
        float v = 0.f;
#pragma unroll
        for (int ch = 0; ch < NCHUNK; ch++)
            v += p[(size_t)ch * BB * NL];
        sA[l * 16 + bb] = v;
    }
    __syncthreads();

    const int bg = tid >> 6;             // batch group of 4
    const int ci = tid & 63;
    const int c  = c0 + ci * 4;
    if (c >= NC) return;                 // NC%4==0 -> full float4 or none

    unsigned long long acc2[4][2];       // [col j][batch pair]
#pragma unroll
    for (int j = 0; j < 4; j++) { acc2[j][0] = 0ull; acc2[j][1] = 0ull; }

    const float* sp = score + (size_t)l0 * NC + c;
    const unsigned long long* ap =
        (const unsigned long long*)(sA + bg * 4);

    // Double-buffered streaming loads: MB float4 loads always in flight
    float4 buf[MB];
#pragma unroll
    for (int i = 0; i < MB; i++)
        buf[i] = __ldcs((const float4*)(sp + (size_t)i * NC));

    for (int lb = 0; lb < LCHUNK; lb += MB) {
        float4 cur[MB];
#pragma unroll
        for (int i = 0; i < MB; i++) cur[i] = buf[i];

        if (lb + MB < LCHUNK) {
#pragma unroll
            for (int i = 0; i < MB; i++)
                buf[i] = __ldcs((const float4*)(sp + (size_t)(lb + MB + i) * NC));
        }

#pragma unroll
        for (int i = 0; i < MB; i++) {
            const int l = lb + i;
            const unsigned long long a01 = ap[l * 8 + 0];
            const unsigned long long a23 = ap[l * 8 + 1];
            const unsigned long long s00 = pk2(cur[i].x, cur[i].x);
            const unsigned long long s11 = pk2(cur[i].y, cur[i].y);
            const unsigned long long s22 = pk2(cur[i].z, cur[i].z);
            const unsigned long long s33 = pk2(cur[i].w, cur[i].w);
            fma2(acc2[0][0], s00, a01); fma2(acc2[0][1], s00, a23);
            fma2(acc2[1][0], s11, a01); fma2(acc2[1][1], s11, a23);
            fma2(acc2[2][0], s22, a01); fma2(acc2[2][1], s22, a23);
            fma2(acc2[3][0], s33, a01); fma2(acc2[3][1], s33, a23);
        }
    }

#pragma unroll
    for (int j = 0; j < 4; j++) {
        float b0, b1, b2, b3;
        upk2(acc2[j][0], b0, b1);
        upk2(acc2[j][1], b2, b3);
        const int bb = bg * 4;
        atomicAdd(out + (bb + 0) * NC + c + j, b0);
        atomicAdd(out + (bb + 1) * NC + c + j, b1);
        atomicAdd(out + (bb + 2) * NC + c + j, b2);
        atomicAdd(out + (bb + 3) * NC + c + j, b3);
    }
}

// ---------------------------------------------------------------------------
extern "C" void kernel_launch(void* const* d_in, const int* in_sizes, int n_in,
                              void* d_out, int out_size)
{
    const float* x     = (const float*)d_in[0];  // (2,16,512,12)
    const float* cuts  = (const float*)d_in[1];  // (12,1)
    const float* score = (const float*)d_in[2];  // (4096,1000)
    float* out = (float*)d_out;                  // (16,1000)

    leaf_kernel<<<BB * NCHUNK, 256>>>(x, cuts, out);
    dim3 g2(NL / LCHUNK, (NC + CTILE - 1) / CTILE);
    gemm_out_kernel<<<g2, 256>>>(score, out);
}

// round 4
// speedup vs baseline: 1.9882x; 1.1218x over previous
#include <cuda_runtime.h>
#include <cstdint>

// Problem constants
#define LL 2
#define BB 16
#define TT 512
#define HH 12
#define NL 4096   // (1+1)^12 leaves
#define NC 1000
#define NCHUNK 16 // token chunks of 32 per batch
#define TOKC 32   // tokens per chunk

// Scratch
__device__ float g_part[NCHUNK * BB * NL];  // [chunk][batch][leaf] (4 MB)
__device__ float g_avg[BB * NL];            // [batch][leaf] (256 KB)

// ---- f32x2 helpers ---------------------------------------------------------
__device__ __forceinline__ unsigned long long pk2(float x, float y) {
    unsigned long long r;
    asm("mov.b64 %0, {%1, %2};" : "=l"(r) : "f"(x), "f"(y));
    return r;
}
__device__ __forceinline__ void fma2(unsigned long long& d,
                                     unsigned long long a,
                                     unsigned long long b) {
    asm("fma.rn.f32x2 %0, %1, %2, %0;" : "+l"(d) : "l"(a), "l"(b));
}
__device__ __forceinline__ void upk2(unsigned long long v, float& lo, float& hi) {
    asm("mov.b64 {%0, %1}, %2;" : "=f"(lo), "=f"(hi) : "l"(v));
}

// ---- cp.async helpers ------------------------------------------------------
__device__ __forceinline__ uint32_t smem_u32(const void* p) {
    uint32_t a;
    asm("{ .reg .u64 t; cvta.to.shared.u64 t, %1; cvt.u32.u64 %0, t; }"
        : "=r"(a) : "l"(p));
    return a;
}
__device__ __forceinline__ void cp_async16(uint32_t dst, const void* src, int sz) {
    asm volatile("cp.async.cg.shared.global [%0], [%1], 16, %2;"
                 :: "r"(dst), "l"(src), "r"(sz));
}
__device__ __forceinline__ void cp_commit() {
    asm volatile("cp.async.commit_group;");
}
template <int N> __device__ __forceinline__ void cp_wait() {
    asm volatile("cp.async.wait_group %0;" :: "n"(N));
}

// ---------------------------------------------------------------------------
// Kernel 1: per-(batch, token-chunk) partial mean-leaf vectors, disjoint STG.
// grid = B * NCHUNK = 256 blocks, 256 threads. Also zeroes `out`.
// ---------------------------------------------------------------------------
__global__ __launch_bounds__(256) void leaf_kernel(
    const float* __restrict__ x, const float* __restrict__ cuts,
    float* __restrict__ out)
{
    const int tid = threadIdx.x;
    const int gid = blockIdx.x * 256 + tid;
    if (gid < BB * NC) out[gid] = 0.f;

    const int b     = blockIdx.x >> 4;
    const int chunk = blockIdx.x & 15;

    __shared__ float P[TOKC * 128];
    __shared__ float sx[TOKC * 12];
    __shared__ float sc[12];

    if (tid < 12) sc[tid] = cuts[tid];

    const float* xl = x + (size_t)(LL - 1) * BB * TT * HH
                        + ((size_t)b * TT + (size_t)chunk * TOKC) * HH;
    for (int i = tid; i < TOKC * 12; i += 256) sx[i] = xl[i];
    __syncthreads();

    for (int e = tid; e < TOKC * 128; e += 256) {
        const int tok  = e >> 7;
        const int half = (e >> 6) & 1;
        const int u    = e & 63;
        const float* xr = sx + tok * 12 + half * 6;
        const float* cr = sc + half * 6;
        float p = 1.f;
#pragma unroll
        for (int i = 0; i < 6; i++) {
            const float xv = xr[i];
            const float f  = ((u >> (5 - i)) & 1) ? fmaf(2.f, xv, -cr[i]) : xv;
            p *= f;
        }
        P[e] = p;
    }
    __syncthreads();

    const int w = tid >> 5, lane = tid & 31;
    unsigned long long acc2[4][2];
#pragma unroll
    for (int p = 0; p < 4; p++) { acc2[p][0] = 0ull; acc2[p][1] = 0ull; }

    for (int tok = 0; tok < TOKC; tok++) {
        const float* Pr = P + tok * 128;
        const float4 pa = *(const float4*)(Pr + 8 * w);
        const float4 pb = *(const float4*)(Pr + 8 * w + 4);
        const float plo0 = Pr[64 + lane];
        const float plo1 = Pr[64 + lane + 32];
        const unsigned long long pl0 = pk2(plo0, plo0);
        const unsigned long long pl1 = pk2(plo1, plo1);
        const unsigned long long ph01 = pk2(pa.x, pa.y);
        const unsigned long long ph23 = pk2(pa.z, pa.w);
        const unsigned long long ph45 = pk2(pb.x, pb.y);
        const unsigned long long ph67 = pk2(pb.z, pb.w);
        fma2(acc2[0][0], ph01, pl0); fma2(acc2[0][1], ph01, pl1);
        fma2(acc2[1][0], ph23, pl0); fma2(acc2[1][1], ph23, pl1);
        fma2(acc2[2][0], ph45, pl0); fma2(acc2[2][1], ph45, pl1);
        fma2(acc2[3][0], ph67, pl0); fma2(acc2[3][1], ph67, pl1);
    }

    const float s = 1.f / (float)TT;
    float* dst = g_part + ((size_t)(chunk * BB + b)) * NL;
#pragma unroll
    for (int p = 0; p < 4; p++) {
        float u0v0, u1v0, u0v1, u1v1;
        upk2(acc2[p][0], u0v0, u1v0);
        upk2(acc2[p][1], u0v1, u1v1);
        const int u0 = 8 * w + 2 * p;
        dst[u0 * 64 + lane]            = u0v0 * s;
        dst[u0 * 64 + lane + 32]       = u0v1 * s;
        dst[(u0 + 1) * 64 + lane]      = u1v0 * s;
        dst[(u0 + 1) * 64 + lane + 32] = u1v1 * s;
    }
}

// ---------------------------------------------------------------------------
// Kernel 2: reduce the 16 chunk partials -> g_avg[16][4096]. 4 MB read.
// ---------------------------------------------------------------------------
__global__ __launch_bounds__(256) void reduce_kernel()
{
    const int i = blockIdx.x * 256 + threadIdx.x;   // 0 .. 65535
    float v = 0.f;
#pragma unroll
    for (int ch = 0; ch < NCHUNK; ch++)
        v += g_part[(size_t)ch * BB * NL + i];
    g_avg[i] = v;
}

// ---------------------------------------------------------------------------
// Kernel 3: out[16,1000] += g_avg[16,4096] @ score[4096,1000].
// grid = (64, 8), 128 threads. LCHUNK=64 rows, CTILE=128 cols.
// Score streamed via 4-stage cp.async pipeline (8 KB per stage).
// Thread owns 1 column x all 16 batches (8 packed f32x2 accumulators).
// ---------------------------------------------------------------------------
#define G_LCH  64
#define G_CT   128
#define SROWS  16   // rows per pipeline stage
#define NSTAGE 4

__global__ __launch_bounds__(128) void gemm_out_kernel(
    const float* __restrict__ score, float* __restrict__ out)
{
    __shared__ float sS[G_LCH * G_CT];   // 32 KB score tile (4 stages x 16 rows)
    __shared__ float sA[G_LCH * 16];     // 4 KB  [l][b]

    const int tid = threadIdx.x;
    const int l0  = blockIdx.x * G_LCH;
    const int c0  = blockIdx.y * G_CT;
    const uint32_t sS_base = smem_u32(sS);

    // Issue all 4 stages of async score loads up front (32 KB in flight).
#pragma unroll
    for (int s = 0; s < NSTAGE; s++) {
#pragma unroll
        for (int t = 0; t < 4; t++) {
            const int k  = tid + t * 128;           // 0..511 chunk id
            const int r  = k >> 5;                  // row within stage 0..15
            const int cc = k & 31;                  // 16B chunk within row
            const int col = c0 + cc * 4;
            const char* src = (const char*)score
                + (size_t)(l0 + s * SROWS + r) * (NC * 4) + (size_t)col * 4;
            const uint32_t dst = sS_base
                + (uint32_t)(((s * SROWS + r) * G_CT + cc * 4) * 4);
            const int sz = (col + 4 <= NC) ? 16 : 0;
            cp_async16(dst, src, sz);
        }
        cp_commit();
    }

    // Build sA from g_avg (L2-hot, 4 KB per block) while loads fly.
    for (int e = tid; e < 16 * G_LCH; e += 128) {
        const int bb = e >> 6;
        const int l  = e & (G_LCH - 1);
        sA[l * 16 + bb] = g_avg[bb * NL + l0 + l];
    }

    unsigned long long acc[8];
#pragma unroll
    for (int p = 0; p < 8; p++) acc[p] = 0ull;

    const int c = c0 + tid;

    // Consume stages
#pragma unroll
    for (int s = 0; s < NSTAGE; s++) {
        if (s == 0) cp_wait<3>();
        else if (s == 1) cp_wait<2>();
        else if (s == 2) cp_wait<1>();
        else cp_wait<0>();
        __syncthreads();

#pragma unroll
        for (int r = 0; r < SROWS; r++) {
            const int l = s * SROWS + r;
            const float sv = sS[l * G_CT + tid];
            const unsigned long long ss = pk2(sv, sv);
            const ulonglong2* ar = (const ulonglong2*)(sA + l * 16);
            const ulonglong2 q0 = ar[0];
            const ulonglong2 q1 = ar[1];
            const ulonglong2 q2 = ar[2];
            const ulonglong2 q3 = ar[3];
            fma2(acc[0], ss, q0.x); fma2(acc[1], ss, q0.y);
            fma2(acc[2], ss, q1.x); fma2(acc[3], ss, q1.y);
            fma2(acc[4], ss, q2.x); fma2(acc[5], ss, q2.y);
            fma2(acc[6], ss, q3.x); fma2(acc[7], ss, q3.y);
        }
    }

    if (c < NC) {
#pragma unroll
        for (int p = 0; p < 8; p++) {
            float blo, bhi;
            upk2(acc[p], blo, bhi);
            atomicAdd(out + (2 * p) * NC + c,     blo);
            atomicAdd(out + (2 * p + 1) * NC + c, bhi);
        }
    }
}

// ---------------------------------------------------------------------------
extern "C" void kernel_launch(void* const* d_in, const int* in_sizes, int n_in,
                              void* d_out, int out_size)
{
    const float* x     = (const float*)d_in[0];  // (2,16,512,12)
    const float* cuts  = (const float*)d_in[1];  // (12,1)
    const float* score = (const float*)d_in[2];  // (4096,1000)
    float* out = (float*)d_out;                  // (16,1000)

    leaf_kernel<<<BB * NCHUNK, 256>>>(x, cuts, out);
    reduce_kernel<<<BB * NL / 256, 256>>>();
    dim3 g3(NL / G_LCH, (NC + G_CT - 1) / G_CT);   // (64, 8)
    gemm_out_kernel<<<g3, 128>>>(score, out);
}